// round 15
// baseline (speedup 1.0000x reference)
#include <cuda_runtime.h>
#include <cstdint>

#define T_    256
#define N_    4096
#define C_    12
#define D_    256
#define K_    12
#define KPAD  136          // 272/2 k-pairs: 128 h + 6 x/onehot + 2 zero pad
#define RB    32
#define NTHR  256
#define NBLK  (N_ / RB)    // 128
#define CH    17           // k-pairs per TMA chunk; 8 chunks = 136
#define NCHK  8
#define CHW   (CH * D_)    // ull per chunk (4352)
#define CHBYTES (CHW * 8)  // 34816
#define GTOT  (2 * T_ * NCHK)   // 4096

typedef unsigned long long ull;

// ---- smem layout (ull units) ----
#define U_W    0                       // 2 chunk buffers
#define U_SH   (U_W + 2 * CHW)         // h_aug [136][32] ull
#define U_WY   (U_SH + KPAD * RB)      // Wy paired [12][128] ull
#define U_BE   (U_WY + 12 * 128)       // enc bias {b,0} [256]
#define U_BD   (U_BE + 256)            // dec bias {b,0} [256]
#define U_YT   (U_BD + 256)            // ytmp 384 floats = 192 ull
#define U_BY   (U_YT + 192)            // by 12 floats (pad 16)
#define U_MB   (U_BY + 8)              // 2 mbarriers
#define U_TOT  (U_MB + 2)
#define SMEM_BYTES (U_TOT * 8)         // ~123 KB

// W pre-paired: g_Wp[phase][kp][d] = {W(d,2kp), W(d,2kp+1)}; kp>=128 -> Wx cols; kp>=134 -> 0
__device__ float2 g_Wp[2][KPAD][D_];

__device__ __forceinline__ void ffma2(ull &d, ull a, ull b) {
    asm("fma.rn.f32x2 %0, %1, %2, %0;" : "+l"(d) : "l"(a), "l"(b));
}
__device__ __forceinline__ void unpack2(ull v, float &lo, float &hi) {
    asm("mov.b64 {%0, %1}, %2;" : "=f"(lo), "=f"(hi) : "l"(v));
}
__device__ __forceinline__ ull pk(float a, float b) {
    ull r; asm("mov.b64 %0, {%1, %2};" : "=l"(r) : "f"(a), "f"(b)); return r;
}
__device__ __forceinline__ float shflx(float v, int m) {
    float r;
    asm("shfl.sync.bfly.b32 %0, %1, %2, 0x1f, 0xffffffff;" : "=f"(r) : "f"(v), "r"(m));
    return r;
}
__device__ __forceinline__ unsigned smem_u32(const void* p) {
    unsigned r;
    asm("{ .reg .u64 t; cvta.to.shared.u64 t, %1; cvt.u32.u64 %0, t; }" : "=r"(r) : "l"(p));
    return r;
}
__device__ __forceinline__ void mbar_init(unsigned mb, unsigned cnt) {
    asm volatile("mbarrier.init.shared.b64 [%0], %1;" :: "r"(mb), "r"(cnt) : "memory");
}
__device__ __forceinline__ void mbar_wait(unsigned mb, unsigned parity) {
    unsigned done;
    asm volatile("{\n\t.reg .pred p;\n\t"
                 "mbarrier.try_wait.parity.acquire.cta.shared::cta.b64 p, [%1], %2;\n\t"
                 "selp.b32 %0, 1, 0, p;\n\t}"
                 : "=r"(done) : "r"(mb), "r"(parity) : "memory");
    if (!done) {
        asm volatile("{\n\t.reg .pred P;\n"
                     "W%=:\n\t"
                     "mbarrier.try_wait.parity.acquire.cta.shared::cta.b64 P, [%0], %1, 0x989680;\n\t"
                     "@P bra.uni D%=;\n\t"
                     "bra.uni W%=;\n"
                     "D%=:\n\t}"
                     :: "r"(mb), "r"(parity) : "memory");
    }
}
__device__ __forceinline__ void tma_issue(unsigned mb, unsigned dst, const void* src) {
    asm volatile("mbarrier.arrive.expect_tx.shared.b64 _, [%0], %1;"
                 :: "r"(mb), "r"((unsigned)CHBYTES) : "memory");
    asm volatile("cp.async.bulk.shared::cluster.global.mbarrier::complete_tx::bytes "
                 "[%0], [%1], %2, [%3];"
                 :: "r"(dst), "l"(src), "r"((unsigned)CHBYTES), "r"(mb) : "memory");
}
// one h value (duplicated k-pair for one row) times 8 outputs
__device__ __forceinline__ void row8(ull* a, ull h,
                                     const ulonglong2 &w0, const ulonglong2 &w1,
                                     const ulonglong2 &w2, const ulonglong2 &w3) {
    ffma2(a[0], h, w0.x); ffma2(a[1], h, w0.y);
    ffma2(a[2], h, w1.x); ffma2(a[3], h, w1.y);
    ffma2(a[4], h, w2.x); ffma2(a[5], h, w2.y);
    ffma2(a[6], h, w3.x); ffma2(a[7], h, w3.y);
}

// ---------------- prep: paired fused weight image ----------------
__global__ void prep_kernel(const float* __restrict__ eWh, const float* __restrict__ eWx,
                            const float* __restrict__ dWh, const float* __restrict__ dWx)
{
    int p  = blockIdx.x / KPAD;
    int kp = blockIdx.x % KPAD;
    int d  = threadIdx.x;
    const float* Wh = p ? dWh : eWh;
    const float* Wx = p ? dWx : eWx;
    int k0 = 2 * kp, k1 = 2 * kp + 1;
    float v0 = (k0 < D_) ? Wh[d * D_ + k0] : ((k0 < D_ + C_) ? Wx[d * C_ + (k0 - D_)] : 0.f);
    float v1 = (k1 < D_) ? Wh[d * D_ + k1] : ((k1 < D_ + C_) ? Wx[d * C_ + (k1 - D_)] : 0.f);
    g_Wp[p][kp][d] = make_float2(v0, v1);
}

// ---------------- main persistent kernel ----------------
extern "C" __global__ void __launch_bounds__(NTHR, 1)
seq2seq_kernel(const float* __restrict__ x,
               const float* __restrict__ ebx, const float* __restrict__ dbx,
               const float* __restrict__ dWy, const float* __restrict__ dby,
               float* __restrict__ out)
{
    extern __shared__ ull smu[];
    ull*   smW = smu + U_W;
    ull*   sh  = smu + U_SH;
    ull*   sWy = smu + U_WY;
    ull*   sbe = smu + U_BE;
    ull*   sbd = smu + U_BD;
    float* yt  = (float*)(smu + U_YT);
    float* sby = (float*)(smu + U_BY);

    const int tid  = threadIdx.x;
    const int lane = tid & 31;
    const int warp = tid >> 5;
    const int r0   = (tid & 7) * 4;       // 4 rows
    const int d0   = (tid >> 3) * 8;      // 8 outputs (ull index == output index)
    const int rowbase = blockIdx.x * RB;

    const unsigned sW_u32 = smem_u32(smu) + U_W * 8;
    const unsigned mb_u32 = smem_u32(smu) + U_MB * 8;

    const int c1 = tid >> 5;              // aug staging (tid<192): pair-col, row
    const int r1 = tid & 31;

    // ---- init ----
    for (int i = tid; i < KPAD * RB; i += NTHR) sh[i] = 0ull;
    for (int i = tid; i < 12 * 128; i += NTHR)  sWy[i] = ((const ull*)dWy)[i];
    for (int i = tid; i < D_; i += NTHR) {
        sbe[i] = pk(ebx[i], 0.f);
        sbd[i] = pk(dbx[i], 0.f);
    }
    if (tid < K_) sby[tid] = dby[tid];
    if (tid == 0) { mbar_init(mb_u32, 1); mbar_init(mb_u32 + 8, 1); }
    __syncthreads();

    // stage x_0 into aug rows (192 slots)
    if (tid < 192) {
        const float2 a = *(const float2*)(x + ((size_t)rowbase + r1) * C_ + 2 * c1);
        sh[(128 + c1) * RB + r1] = pk(a.x, a.y);
    }
    if (tid == 0) {   // prime chunks g=0 (buf0), g=1 (buf1), phase 0
        tma_issue(mb_u32,     sW_u32,           (const char*)g_Wp);
        tma_issue(mb_u32 + 8, sW_u32 + CHBYTES, (const char*)g_Wp + (size_t)CH * D_ * 8);
    }
    __syncthreads();

    ull acc[32];

    for (int t = 0; t < 2 * T_; ++t) {
        const bool dec = (t >= T_);

        // prefetch next x slice into regs (encoder)
        ull xv = 0ull;
        if (!dec && (t + 1) < T_ && tid < 192) {
            const float2 a = *(const float2*)(x + ((size_t)(t + 1) * N_ + rowbase + r1) * C_ + 2 * c1);
            xv = pk(a.x, a.y);
        }

        // acc init = {bias, 0}
        {
            const ulonglong2* bp = (const ulonglong2*)((dec ? sbd : sbe) + d0);
            ulonglong2 b01 = bp[0], b23 = bp[1], b45 = bp[2], b67 = bp[3];
            ull bj[8] = {b01.x, b01.y, b23.x, b23.y, b45.x, b45.y, b67.x, b67.y};
            #pragma unroll
            for (int i = 0; i < 4; ++i)
                #pragma unroll
                for (int j = 0; j < 8; ++j) acc[i * 8 + j] = bj[j];
        }

        // ---- GEMM: 8 chunks of 17 kp; depth-1 register pipeline ----
        #pragma unroll 1
        for (int c = 0; c < NCHK; ++c) {
            const int g = t * NCHK + c;
            const int b = g & 1;
            mbar_wait(mb_u32 + b * 8, (unsigned)((g >> 1) & 1));

            const ull* wb = smW + (size_t)b * CHW + d0;
            const ull* hb = sh + (size_t)(c * CH) * RB + r0;

            // prime kp0 into A
            const ulonglong2* wq = (const ulonglong2*)wb;
            const ulonglong2* hq = (const ulonglong2*)hb;
            ulonglong2 wA0 = wq[0], wA1 = wq[1], wA2 = wq[2], wA3 = wq[3];
            ulonglong2 hA0 = hq[0], hA1 = hq[1];

            #pragma unroll 2
            for (int kk = 0; kk < 16; kk += 2) {
                // load kp kk+1 into B
                const ulonglong2* wqB = (const ulonglong2*)(wb + (size_t)(kk + 1) * D_);
                const ulonglong2* hqB = (const ulonglong2*)(hb + (size_t)(kk + 1) * RB);
                ulonglong2 wB0 = wqB[0], wB1 = wqB[1], wB2 = wqB[2], wB3 = wqB[3];
                ulonglong2 hB0 = hqB[0], hB1 = hqB[1];

                // compute kp kk (A)
                row8(acc + 0,  hA0.x, wA0, wA1, wA2, wA3);
                row8(acc + 8,  hA0.y, wA0, wA1, wA2, wA3);
                row8(acc + 16, hA1.x, wA0, wA1, wA2, wA3);
                row8(acc + 24, hA1.y, wA0, wA1, wA2, wA3);

                // load kp kk+2 into A (kk=14 -> kp16, last in chunk: no over-read)
                const ulonglong2* wqA = (const ulonglong2*)(wb + (size_t)(kk + 2) * D_);
                const ulonglong2* hqA = (const ulonglong2*)(hb + (size_t)(kk + 2) * RB);
                wA0 = wqA[0]; wA1 = wqA[1]; wA2 = wqA[2]; wA3 = wqA[3];
                hA0 = hqA[0]; hA1 = hqA[1];

                // compute kp kk+1 (B)
                row8(acc + 0,  hB0.x, wB0, wB1, wB2, wB3);
                row8(acc + 8,  hB0.y, wB0, wB1, wB2, wB3);
                row8(acc + 16, hB1.x, wB0, wB1, wB2, wB3);
                row8(acc + 24, hB1.y, wB0, wB1, wB2, wB3);
            }
            // tail: compute kp16 (A)
            row8(acc + 0,  hA0.x, wA0, wA1, wA2, wA3);
            row8(acc + 8,  hA0.y, wA0, wA1, wA2, wA3);
            row8(acc + 16, hA1.x, wA0, wA1, wA2, wA3);
            row8(acc + 24, hA1.y, wA0, wA1, wA2, wA3);

            __syncthreads();   // buffer b consumed by all threads

            if (tid == 0 && (g + 2) < GTOT) {
                const int g2 = g + 2;
                const int t2 = g2 >> 3, c2 = g2 & 7;
                const int ph = (t2 >= T_) ? 1 : 0;
                tma_issue(mb_u32 + b * 8, sW_u32 + b * CHBYTES,
                          (const char*)g_Wp + ((size_t)ph * KPAD + c2 * CH) * D_ * 8);
            }
        }

        // ---- epilogue: h = relu(lo+hi), store paired h ----
        #pragma unroll
        for (int j2 = 0; j2 < 4; ++j2) {
            float4* dst = (float4*)(sh + (size_t)((d0 >> 1) + j2) * RB + r0);
            #pragma unroll
            for (int i2 = 0; i2 < 2; ++i2) {
                float a0, b0, a1, b1, a2, b2, a3, b3;
                unpack2(acc[(2 * i2) * 8 + 2 * j2],         a0, b0);
                unpack2(acc[(2 * i2) * 8 + 2 * j2 + 1],     a1, b1);
                unpack2(acc[(2 * i2 + 1) * 8 + 2 * j2],     a2, b2);
                unpack2(acc[(2 * i2 + 1) * 8 + 2 * j2 + 1], a3, b3);
                dst[i2] = make_float4(fmaxf(a0 + b0, 0.f), fmaxf(a1 + b1, 0.f),
                                      fmaxf(a2 + b2, 0.f), fmaxf(a3 + b3, 0.f));
            }
        }
        if (tid < 192) {
            if (!dec) {   // stage x_{t+1} or SOS (col 10 -> pair 5 = {1,0})
                sh[(128 + c1) * RB + r1] =
                    (t + 1 < T_) ? xv : ((c1 == 5) ? pk(1.f, 0.f) : 0ull);
            } else {      // clear previous one-hot
                sh[(128 + c1) * RB + r1] = 0ull;
            }
        }
        __syncthreads();   // publish new h (+aug/zero)

        // ---- decoder: tiled y = h @ Wy^T + by, argmax, one-hot feedback ----
        if (dec) {
            const int kg = lane & 3;          // k in {kg, kg+4, kg+8}
            const int mg = lane >> 2;         // m-chunk [16*mg, 16*mg+16)
            const ull* hb = sh + 4 * warp;    // rows 4*warp..+3 of NEW h
            const ull* w0 = sWy + kg * 128;
            const ull* w1 = sWy + (kg + 4) * 128;
            const ull* w2 = sWy + (kg + 8) * 128;
            ull a[12];
            #pragma unroll
            for (int q = 0; q < 12; ++q) a[q] = 0ull;
            const int mbase = mg * 16;
            #pragma unroll 4
            for (int mm = 0; mm < 16; ++mm) {
                const int m = mbase + mm;
                const ulonglong2* hp = (const ulonglong2*)(hb + (size_t)m * RB);
                ulonglong2 hA = hp[0], hB = hp[1];
                ull hr[4] = {hA.x, hA.y, hB.x, hB.y};
                ull wv0 = w0[m], wv1 = w1[m], wv2 = w2[m];
                #pragma unroll
                for (int i = 0; i < 4; ++i) {
                    ffma2(a[i * 3 + 0], hr[i], wv0);
                    ffma2(a[i * 3 + 1], hr[i], wv1);
                    ffma2(a[i * 3 + 2], hr[i], wv2);
                }
            }
            float v[12];
            #pragma unroll
            for (int q = 0; q < 12; ++q) {
                float lo, hi; unpack2(a[q], lo, hi);
                v[q] = lo + hi;
            }
            #pragma unroll
            for (int q = 0; q < 12; ++q) {
                v[q] += shflx(v[q], 4);
                v[q] += shflx(v[q], 8);
                v[q] += shflx(v[q], 16);
            }
            if (mg == 0) {
                #pragma unroll
                for (int i = 0; i < 4; ++i) {
                    yt[(4 * warp + i) * 12 + kg]     = v[i * 3 + 0] + sby[kg];
                    yt[(4 * warp + i) * 12 + kg + 4] = v[i * 3 + 1] + sby[kg + 4];
                    yt[(4 * warp + i) * 12 + kg + 8] = v[i * 3 + 2] + sby[kg + 8];
                }
            }
            __syncthreads();   // yt complete
            if (tid < 32) {
                const float* yr = yt + tid * 12;
                float vv[12];
                #pragma unroll
                for (int q = 0; q < 3; ++q) {
                    float4 fv = *(const float4*)(yr + 4 * q);
                    vv[4 * q] = fv.x; vv[4 * q + 1] = fv.y;
                    vv[4 * q + 2] = fv.z; vv[4 * q + 3] = fv.w;
                }
                float best = vv[0]; int sel = 0;
                #pragma unroll
                for (int q = 1; q < 12; ++q)
                    if (vv[q] > best) { best = vv[q]; sel = q; }   // first-max wins
                float* og = out + ((size_t)(t - T_) * N_ + rowbase + tid) * K_;
                *(float4*)(og)     = make_float4(vv[0], vv[1], vv[2],  vv[3]);
                *(float4*)(og + 4) = make_float4(vv[4], vv[5], vv[6],  vv[7]);
                *(float4*)(og + 8) = make_float4(vv[8], vv[9], vv[10], vv[11]);
                // one-hot into aug (rows zeroed at epilogue); visible to next
                // step's chunk-7 reads via 7 intervening chunk barriers.
                sh[(128 + (sel >> 1)) * RB + tid] = (sel & 1) ? pk(0.f, 1.f) : pk(1.f, 0.f);
            }
            // no trailing barrier needed
        }
    }
}

extern "C" void kernel_launch(void* const* d_in, const int* in_sizes, int n_in,
                              void* d_out, int out_size) {
    const float* x   = (const float*)d_in[0];
    const float* eWx = (const float*)d_in[1];
    const float* ebx = (const float*)d_in[2];
    const float* eWh = (const float*)d_in[3];
    const float* dWx = (const float*)d_in[6];
    const float* dbx = (const float*)d_in[7];
    const float* dWh = (const float*)d_in[8];
    const float* dWy = (const float*)d_in[9];
    const float* dby = (const float*)d_in[10];

    prep_kernel<<<2 * KPAD, D_>>>(eWh, eWx, dWh, dWx);

    cudaFuncSetAttribute(seq2seq_kernel,
                         cudaFuncAttributeMaxDynamicSharedMemorySize, SMEM_BYTES);
    seq2seq_kernel<<<NBLK, NTHR, SMEM_BYTES>>>(
        x, ebx, dbx, dWy, dby, (float*)d_out);
}

// round 16
// speedup vs baseline: 1.1166x; 1.1166x over previous
#include <cuda_runtime.h>
#include <cstdint>

#define T_    256
#define N_    4096
#define C_    12
#define D_    256
#define K_    12
#define KPAD  136          // 272/2 k-pairs: 128 h + 6 x/onehot + 2 zero pad
#define RB    32
#define NTHR  256
#define NBLK  (N_ / RB)    // 128
#define CH    17           // k-pairs per TMA chunk; 8 chunks = 136
#define NCHK  8
#define CHW   (CH * D_)    // ull per chunk (4352)
#define CHBYTES (CHW * 8)  // 34816
#define GTOT  (2 * T_ * NCHK)   // 4096

typedef unsigned long long ull;

// ---- smem layout (ull units) ----
#define U_W    0                       // 2 chunk buffers
#define U_SH   (U_W + 2 * CHW)         // h_aug [136][32] ull
#define U_WY   (U_SH + KPAD * RB)      // Wy paired [12][128] ull
#define U_BE   (U_WY + 12 * 128)       // enc bias {b,0} [256]
#define U_BD   (U_BE + 256)            // dec bias {b,0} [256]
#define U_YT   (U_BD + 256)            // ytmp 384 floats = 192 ull
#define U_BY   (U_YT + 192)            // by 12 floats (pad 16)
#define U_MB   (U_BY + 8)              // 2 mbarriers
#define U_TOT  (U_MB + 2)
#define SMEM_BYTES (U_TOT * 8)         // ~123 KB

// W pre-paired: g_Wp[phase][kp][d] = {W(d,2kp), W(d,2kp+1)}; kp>=128 -> Wx cols; kp>=134 -> 0
__device__ float2 g_Wp[2][KPAD][D_];

__device__ __forceinline__ void ffma2(ull &d, ull a, ull b) {
    asm("fma.rn.f32x2 %0, %1, %2, %0;" : "+l"(d) : "l"(a), "l"(b));
}
__device__ __forceinline__ void unpack2(ull v, float &lo, float &hi) {
    asm("mov.b64 {%0, %1}, %2;" : "=f"(lo), "=f"(hi) : "l"(v));
}
__device__ __forceinline__ ull pk(float a, float b) {
    ull r; asm("mov.b64 %0, {%1, %2};" : "=l"(r) : "f"(a), "f"(b)); return r;
}
__device__ __forceinline__ float shflx(float v, int m) {
    float r;
    asm("shfl.sync.bfly.b32 %0, %1, %2, 0x1f, 0xffffffff;" : "=f"(r) : "f"(v), "r"(m));
    return r;
}
__device__ __forceinline__ unsigned smem_u32(const void* p) {
    unsigned r;
    asm("{ .reg .u64 t; cvta.to.shared.u64 t, %1; cvt.u32.u64 %0, t; }" : "=r"(r) : "l"(p));
    return r;
}
__device__ __forceinline__ void mbar_init(unsigned mb, unsigned cnt) {
    asm volatile("mbarrier.init.shared.b64 [%0], %1;" :: "r"(mb), "r"(cnt) : "memory");
}
__device__ __forceinline__ void mbar_wait(unsigned mb, unsigned parity) {
    unsigned done;
    asm volatile("{\n\t.reg .pred p;\n\t"
                 "mbarrier.try_wait.parity.acquire.cta.shared::cta.b64 p, [%1], %2;\n\t"
                 "selp.b32 %0, 1, 0, p;\n\t}"
                 : "=r"(done) : "r"(mb), "r"(parity) : "memory");
    if (!done) {
        asm volatile("{\n\t.reg .pred P;\n"
                     "W%=:\n\t"
                     "mbarrier.try_wait.parity.acquire.cta.shared::cta.b64 P, [%0], %1, 0x989680;\n\t"
                     "@P bra.uni D%=;\n\t"
                     "bra.uni W%=;\n"
                     "D%=:\n\t}"
                     :: "r"(mb), "r"(parity) : "memory");
    }
}
__device__ __forceinline__ void tma_issue(unsigned mb, unsigned dst, const void* src) {
    asm volatile("mbarrier.arrive.expect_tx.shared.b64 _, [%0], %1;"
                 :: "r"(mb), "r"((unsigned)CHBYTES) : "memory");
    asm volatile("cp.async.bulk.shared::cluster.global.mbarrier::complete_tx::bytes "
                 "[%0], [%1], %2, [%3];"
                 :: "r"(dst), "l"(src), "r"((unsigned)CHBYTES), "r"(mb) : "memory");
}
// one h value (duplicated k-pair for one row) times 8 outputs
__device__ __forceinline__ void row8(ull* a, ull h,
                                     const ulonglong2 &w0, const ulonglong2 &w1,
                                     const ulonglong2 &w2, const ulonglong2 &w3) {
    ffma2(a[0], h, w0.x); ffma2(a[1], h, w0.y);
    ffma2(a[2], h, w1.x); ffma2(a[3], h, w1.y);
    ffma2(a[4], h, w2.x); ffma2(a[5], h, w2.y);
    ffma2(a[6], h, w3.x); ffma2(a[7], h, w3.y);
}

// ---------------- prep: paired fused weight image ----------------
__global__ void prep_kernel(const float* __restrict__ eWh, const float* __restrict__ eWx,
                            const float* __restrict__ dWh, const float* __restrict__ dWx)
{
    int p  = blockIdx.x / KPAD;
    int kp = blockIdx.x % KPAD;
    int d  = threadIdx.x;
    const float* Wh = p ? dWh : eWh;
    const float* Wx = p ? dWx : eWx;
    int k0 = 2 * kp, k1 = 2 * kp + 1;
    float v0 = (k0 < D_) ? Wh[d * D_ + k0] : ((k0 < D_ + C_) ? Wx[d * C_ + (k0 - D_)] : 0.f);
    float v1 = (k1 < D_) ? Wh[d * D_ + k1] : ((k1 < D_ + C_) ? Wx[d * C_ + (k1 - D_)] : 0.f);
    g_Wp[p][kp][d] = make_float2(v0, v1);
}

// ---------------- main persistent kernel ----------------
extern "C" __global__ void __launch_bounds__(NTHR, 1)
seq2seq_kernel(const float* __restrict__ x,
               const float* __restrict__ ebx, const float* __restrict__ dbx,
               const float* __restrict__ dWy, const float* __restrict__ dby,
               float* __restrict__ out)
{
    extern __shared__ ull smu[];
    ull*   smW = smu + U_W;
    ull*   sh  = smu + U_SH;
    ull*   sWy = smu + U_WY;
    ull*   sbe = smu + U_BE;
    ull*   sbd = smu + U_BD;
    float* yt  = (float*)(smu + U_YT);
    float* sby = (float*)(smu + U_BY);

    const int tid  = threadIdx.x;
    const int lane = tid & 31;
    const int warp = tid >> 5;
    const int g8   = lane >> 3;           // output group 0..3
    const int s    = lane & 7;            // row group 0..7
    const int rowbase = blockIdx.x * RB;

    // lane->work map (wavefront-optimal):
    //   outputs: slots wOff + {0,1, 8,9, 16,17, 24,25}  (wOff = warp*32 + 2*g8)
    //   rows:    {2s, 2s+1, 16+2s, 17+2s}
    const int wOff = warp * 32 + 2 * g8;
    const int hOffA = 2 * s;              // rows 2s, 2s+1
    const int hOffB = 16 + 2 * s;         // rows 16+2s, 17+2s

    const unsigned sW_u32 = smem_u32(smu) + U_W * 8;
    const unsigned mb_u32 = smem_u32(smu) + U_MB * 8;

    const int c1 = tid >> 5;              // aug staging (tid<192): pair-col, row
    const int r1 = tid & 31;

    // ---- init ----
    for (int i = tid; i < KPAD * RB; i += NTHR) sh[i] = 0ull;
    for (int i = tid; i < 12 * 128; i += NTHR)  sWy[i] = ((const ull*)dWy)[i];
    for (int i = tid; i < D_; i += NTHR) {
        sbe[i] = pk(ebx[i], 0.f);
        sbd[i] = pk(dbx[i], 0.f);
    }
    if (tid < K_) sby[tid] = dby[tid];
    if (tid == 0) { mbar_init(mb_u32, 1); mbar_init(mb_u32 + 8, 1); }
    __syncthreads();

    // stage x_0 into aug rows (192 slots)
    if (tid < 192) {
        const float2 a = *(const float2*)(x + ((size_t)rowbase + r1) * C_ + 2 * c1);
        sh[(128 + c1) * RB + r1] = pk(a.x, a.y);
    }
    if (tid == 0) {   // prime chunks g=0 (buf0), g=1 (buf1), phase 0
        tma_issue(mb_u32,     sW_u32,           (const char*)g_Wp);
        tma_issue(mb_u32 + 8, sW_u32 + CHBYTES, (const char*)g_Wp + (size_t)CH * D_ * 8);
    }
    __syncthreads();

    ull acc[32];

    for (int t = 0; t < 2 * T_; ++t) {
        const bool dec = (t >= T_);

        // prefetch next x slice into regs (encoder)
        ull xv = 0ull;
        if (!dec && (t + 1) < T_ && tid < 192) {
            const float2 a = *(const float2*)(x + ((size_t)(t + 1) * N_ + rowbase + r1) * C_ + 2 * c1);
            xv = pk(a.x, a.y);
        }

        // acc init = {bias, 0} ; bias slots follow the W slot map
        {
            const ull* bp = (dec ? sbd : sbe) + wOff;
            ulonglong2 b01 = *(const ulonglong2*)(bp);
            ulonglong2 b23 = *(const ulonglong2*)(bp + 8);
            ulonglong2 b45 = *(const ulonglong2*)(bp + 16);
            ulonglong2 b67 = *(const ulonglong2*)(bp + 24);
            ull bj[8] = {b01.x, b01.y, b23.x, b23.y, b45.x, b45.y, b67.x, b67.y};
            #pragma unroll
            for (int i = 0; i < 4; ++i)
                #pragma unroll
                for (int j = 0; j < 8; ++j) acc[i * 8 + j] = bj[j];
        }

        // ---- GEMM: 8 chunks of 17 kp; depth-1 register pipeline ----
        #pragma unroll 1
        for (int c = 0; c < NCHK; ++c) {
            const int g = t * NCHK + c;
            const int b = g & 1;
            mbar_wait(mb_u32 + b * 8, (unsigned)((g >> 1) & 1));

            const ull* wb = smW + (size_t)b * CHW + wOff;
            const ull* hb = sh + (size_t)(c * CH) * RB;

            // prime kp0 into A
            {
                const ull* wq = wb;
                ulonglong2 wA0 = *(const ulonglong2*)(wq);
                ulonglong2 wA1 = *(const ulonglong2*)(wq + 8);
                ulonglong2 wA2 = *(const ulonglong2*)(wq + 16);
                ulonglong2 wA3 = *(const ulonglong2*)(wq + 24);
                ulonglong2 hA0 = *(const ulonglong2*)(hb + hOffA);
                ulonglong2 hA1 = *(const ulonglong2*)(hb + hOffB);

                #pragma unroll 2
                for (int kk = 0; kk < 16; kk += 2) {
                    // load kp kk+1 into B
                    const ull* wqB = wb + (size_t)(kk + 1) * D_;
                    const ull* hqB = hb + (size_t)(kk + 1) * RB;
                    ulonglong2 wB0 = *(const ulonglong2*)(wqB);
                    ulonglong2 wB1 = *(const ulonglong2*)(wqB + 8);
                    ulonglong2 wB2 = *(const ulonglong2*)(wqB + 16);
                    ulonglong2 wB3 = *(const ulonglong2*)(wqB + 24);
                    ulonglong2 hB0 = *(const ulonglong2*)(hqB + hOffA);
                    ulonglong2 hB1 = *(const ulonglong2*)(hqB + hOffB);

                    // compute kp kk (A)
                    row8(acc + 0,  hA0.x, wA0, wA1, wA2, wA3);
                    row8(acc + 8,  hA0.y, wA0, wA1, wA2, wA3);
                    row8(acc + 16, hA1.x, wA0, wA1, wA2, wA3);
                    row8(acc + 24, hA1.y, wA0, wA1, wA2, wA3);

                    // load kp kk+2 into A (kk=14 -> kp16, last in chunk: in-bounds)
                    const ull* wqA = wb + (size_t)(kk + 2) * D_;
                    const ull* hqA = hb + (size_t)(kk + 2) * RB;
                    wA0 = *(const ulonglong2*)(wqA);
                    wA1 = *(const ulonglong2*)(wqA + 8);
                    wA2 = *(const ulonglong2*)(wqA + 16);
                    wA3 = *(const ulonglong2*)(wqA + 24);
                    hA0 = *(const ulonglong2*)(hqA + hOffA);
                    hA1 = *(const ulonglong2*)(hqA + hOffB);

                    // compute kp kk+1 (B)
                    row8(acc + 0,  hB0.x, wB0, wB1, wB2, wB3);
                    row8(acc + 8,  hB0.y, wB0, wB1, wB2, wB3);
                    row8(acc + 16, hB1.x, wB0, wB1, wB2, wB3);
                    row8(acc + 24, hB1.y, wB0, wB1, wB2, wB3);
                }
                // tail: compute kp16 (A)
                row8(acc + 0,  hA0.x, wA0, wA1, wA2, wA3);
                row8(acc + 8,  hA0.y, wA0, wA1, wA2, wA3);
                row8(acc + 16, hA1.x, wA0, wA1, wA2, wA3);
                row8(acc + 24, hA1.y, wA0, wA1, wA2, wA3);
            }

            __syncthreads();   // buffer b consumed by all threads

            if (tid == 0 && (g + 2) < GTOT) {
                const int g2 = g + 2;
                const int t2 = g2 >> 3, c2 = g2 & 7;
                const int ph = (t2 >= T_) ? 1 : 0;
                tma_issue(mb_u32 + b * 8, sW_u32 + b * CHBYTES,
                          (const char*)g_Wp + ((size_t)ph * KPAD + c2 * CH) * D_ * 8);
            }
        }

        // ---- epilogue: h = relu(lo+hi), store paired h ----
        // thread's output-pairs: m = 16*warp + 4*j2 + g8 ; rows {2s,2s+1} and {16+2s,17+2s}
        #pragma unroll
        for (int j2 = 0; j2 < 4; ++j2) {
            const int m = 16 * warp + 4 * j2 + g8;
            float a0, b0, a1, b1, a2, b2, a3, b3;
            // rows A (2s, 2s+1): acc rows i=0,1
            unpack2(acc[0 * 8 + 2 * j2],     a0, b0);
            unpack2(acc[0 * 8 + 2 * j2 + 1], a1, b1);
            unpack2(acc[1 * 8 + 2 * j2],     a2, b2);
            unpack2(acc[1 * 8 + 2 * j2 + 1], a3, b3);
            *(float4*)(sh + (size_t)m * RB + hOffA) =
                make_float4(fmaxf(a0 + b0, 0.f), fmaxf(a1 + b1, 0.f),
                            fmaxf(a2 + b2, 0.f), fmaxf(a3 + b3, 0.f));
            // rows B (16+2s, 17+2s): acc rows i=2,3
            unpack2(acc[2 * 8 + 2 * j2],     a0, b0);
            unpack2(acc[2 * 8 + 2 * j2 + 1], a1, b1);
            unpack2(acc[3 * 8 + 2 * j2],     a2, b2);
            unpack2(acc[3 * 8 + 2 * j2 + 1], a3, b3);
            *(float4*)(sh + (size_t)m * RB + hOffB) =
                make_float4(fmaxf(a0 + b0, 0.f), fmaxf(a1 + b1, 0.f),
                            fmaxf(a2 + b2, 0.f), fmaxf(a3 + b3, 0.f));
        }
        if (tid < 192) {
            if (!dec) {   // stage x_{t+1} or SOS (col 10 -> pair 5 = {1,0})
                sh[(128 + c1) * RB + r1] =
                    (t + 1 < T_) ? xv : ((c1 == 5) ? pk(1.f, 0.f) : 0ull);
            } else {      // clear previous one-hot
                sh[(128 + c1) * RB + r1] = 0ull;
            }
        }
        __syncthreads();   // publish new h (+aug/zero)

        // ---- decoder: tiled y = h @ Wy^T + by, argmax, one-hot feedback ----
        if (dec) {
            const int kg = lane & 3;          // k in {kg, kg+4, kg+8}
            const int mg = lane >> 2;         // m-chunk [16*mg, 16*mg+16)
            const ull* hb = sh + 4 * warp;    // rows 4*warp..+3 of NEW h
            const ull* w0 = sWy + kg * 128;
            const ull* w1 = sWy + (kg + 4) * 128;
            const ull* w2 = sWy + (kg + 8) * 128;
            ull a[12];
            #pragma unroll
            for (int q = 0; q < 12; ++q) a[q] = 0ull;
            const int mbase = mg * 16;
            #pragma unroll 4
            for (int mm = 0; mm < 16; ++mm) {
                const int m = mbase + mm;
                const ulonglong2* hp = (const ulonglong2*)(hb + (size_t)m * RB);
                ulonglong2 hA = hp[0], hB = hp[1];
                ull hr[4] = {hA.x, hA.y, hB.x, hB.y};
                ull wv0 = w0[m], wv1 = w1[m], wv2 = w2[m];
                #pragma unroll
                for (int i = 0; i < 4; ++i) {
                    ffma2(a[i * 3 + 0], hr[i], wv0);
                    ffma2(a[i * 3 + 1], hr[i], wv1);
                    ffma2(a[i * 3 + 2], hr[i], wv2);
                }
            }
            float v[12];
            #pragma unroll
            for (int q = 0; q < 12; ++q) {
                float lo, hi; unpack2(a[q], lo, hi);
                v[q] = lo + hi;
            }
            #pragma unroll
            for (int q = 0; q < 12; ++q) {
                v[q] += shflx(v[q], 4);
                v[q] += shflx(v[q], 8);
                v[q] += shflx(v[q], 16);
            }
            if (mg == 0) {
                #pragma unroll
                for (int i = 0; i < 4; ++i) {
                    yt[(4 * warp + i) * 12 + kg]     = v[i * 3 + 0] + sby[kg];
                    yt[(4 * warp + i) * 12 + kg + 4] = v[i * 3 + 1] + sby[kg + 4];
                    yt[(4 * warp + i) * 12 + kg + 8] = v[i * 3 + 2] + sby[kg + 8];
                }
            }
            __syncthreads();   // yt complete
            if (tid < 32) {
                const float* yr = yt + tid * 12;
                float vv[12];
                #pragma unroll
                for (int q = 0; q < 3; ++q) {
                    float4 fv = *(const float4*)(yr + 4 * q);
                    vv[4 * q] = fv.x; vv[4 * q + 1] = fv.y;
                    vv[4 * q + 2] = fv.z; vv[4 * q + 3] = fv.w;
                }
                float best = vv[0]; int sel = 0;
                #pragma unroll
                for (int q = 1; q < 12; ++q)
                    if (vv[q] > best) { best = vv[q]; sel = q; }   // first-max wins
                float* og = out + ((size_t)(t - T_) * N_ + rowbase + tid) * K_;
                *(float4*)(og)     = make_float4(vv[0], vv[1], vv[2],  vv[3]);
                *(float4*)(og + 4) = make_float4(vv[4], vv[5], vv[6],  vv[7]);
                *(float4*)(og + 8) = make_float4(vv[8], vv[9], vv[10], vv[11]);
                // one-hot into aug (rows zeroed at epilogue); visible to next
                // step's chunk-7 reads via 7 intervening chunk barriers.
                sh[(128 + (sel >> 1)) * RB + tid] = (sel & 1) ? pk(0.f, 1.f) : pk(1.f, 0.f);
            }
            // no trailing barrier needed
        }
    }
}

extern "C" void kernel_launch(void* const* d_in, const int* in_sizes, int n_in,
                              void* d_out, int out_size) {
    const float* x   = (const float*)d_in[0];
    const float* eWx = (const float*)d_in[1];
    const float* ebx = (const float*)d_in[2];
    const float* eWh = (const float*)d_in[3];
    const float* dWx = (const float*)d_in[6];
    const float* dbx = (const float*)d_in[7];
    const float* dWh = (const float*)d_in[8];
    const float* dWy = (const float*)d_in[9];
    const float* dby = (const float*)d_in[10];

    prep_kernel<<<2 * KPAD, D_>>>(eWh, eWx, dWh, dWx);

    cudaFuncSetAttribute(seq2seq_kernel,
                         cudaFuncAttributeMaxDynamicSharedMemorySize, SMEM_BYTES);
    seq2seq_kernel<<<NBLK, NTHR, SMEM_BYTES>>>(
        x, ebx, dbx, dWy, dby, (float*)d_out);
}

// round 17
// speedup vs baseline: 1.1360x; 1.0174x over previous
#include <cuda_runtime.h>
#include <cstdint>

#define T_    256
#define N_    4096
#define C_    12
#define D_    256
#define K_    12
#define KPAD  136          // 272/2 k-pairs: 128 h + 6 x/onehot + 2 zero pad
#define RB    32
#define NTHR  256
#define NBLK  (N_ / RB)    // 128
#define CH    34           // k-pairs per TMA chunk; 4 chunks = 136
#define NCHK  4
#define CHW   (CH * D_)    // ull per chunk (8704)
#define CHBYTES (CHW * 8)  // 69632
#define GTOT  (2 * T_ * NCHK)   // 2048

typedef unsigned long long ull;

// ---- smem layout (ull units) ----
#define U_W    0                       // 2 chunk buffers (2*8704 ull = 139 KB)
#define U_SH   (U_W + 2 * CHW)         // h_aug [136][32] ull
#define U_WY   (U_SH + KPAD * RB)      // Wy paired [12][128] ull
#define U_BE   (U_WY + 12 * 128)       // enc bias {b,0} [256]
#define U_BD   (U_BE + 256)            // dec bias {b,0} [256]
#define U_YT   (U_BD + 256)            // ytmp 384 floats = 192 ull
#define U_BY   (U_YT + 192)            // by 12 floats (pad 16)
#define U_MB   (U_BY + 8)              // data[0..1], consume[0..1]
#define U_TOT  (U_MB + 4)
#define SMEM_BYTES (U_TOT * 8)         // ~192 KB

// W pre-paired: g_Wp[phase][kp][d] = {W(d,2kp), W(d,2kp+1)}; kp>=128 -> Wx cols; kp>=134 -> 0
__device__ float2 g_Wp[2][KPAD][D_];

__device__ __forceinline__ void ffma2(ull &d, ull a, ull b) {
    asm("fma.rn.f32x2 %0, %1, %2, %0;" : "+l"(d) : "l"(a), "l"(b));
}
__device__ __forceinline__ void unpack2(ull v, float &lo, float &hi) {
    asm("mov.b64 {%0, %1}, %2;" : "=f"(lo), "=f"(hi) : "l"(v));
}
__device__ __forceinline__ ull pk(float a, float b) {
    ull r; asm("mov.b64 %0, {%1, %2};" : "=l"(r) : "f"(a), "f"(b)); return r;
}
__device__ __forceinline__ float shflx(float v, int m) {
    float r;
    asm("shfl.sync.bfly.b32 %0, %1, %2, 0x1f, 0xffffffff;" : "=f"(r) : "f"(v), "r"(m));
    return r;
}
__device__ __forceinline__ unsigned smem_u32(const void* p) {
    unsigned r;
    asm("{ .reg .u64 t; cvta.to.shared.u64 t, %1; cvt.u32.u64 %0, t; }" : "=r"(r) : "l"(p));
    return r;
}
__device__ __forceinline__ void mbar_init(unsigned mb, unsigned cnt) {
    asm volatile("mbarrier.init.shared.b64 [%0], %1;" :: "r"(mb), "r"(cnt) : "memory");
}
__device__ __forceinline__ void mbar_arrive(unsigned mb) {
    asm volatile("mbarrier.arrive.shared.b64 _, [%0];" :: "r"(mb) : "memory");
}
__device__ __forceinline__ void mbar_wait(unsigned mb, unsigned parity) {
    unsigned done;
    asm volatile("{\n\t.reg .pred p;\n\t"
                 "mbarrier.try_wait.parity.acquire.cta.shared::cta.b64 p, [%1], %2;\n\t"
                 "selp.b32 %0, 1, 0, p;\n\t}"
                 : "=r"(done) : "r"(mb), "r"(parity) : "memory");
    if (!done) {
        asm volatile("{\n\t.reg .pred P;\n"
                     "W%=:\n\t"
                     "mbarrier.try_wait.parity.acquire.cta.shared::cta.b64 P, [%0], %1, 0x989680;\n\t"
                     "@P bra.uni D%=;\n\t"
                     "bra.uni W%=;\n"
                     "D%=:\n\t}"
                     :: "r"(mb), "r"(parity) : "memory");
    }
}
__device__ __forceinline__ void tma_issue(unsigned mb, unsigned dst, const void* src) {
    asm volatile("mbarrier.arrive.expect_tx.shared.b64 _, [%0], %1;"
                 :: "r"(mb), "r"((unsigned)CHBYTES) : "memory");
    asm volatile("cp.async.bulk.shared::cluster.global.mbarrier::complete_tx::bytes "
                 "[%0], [%1], %2, [%3];"
                 :: "r"(dst), "l"(src), "r"((unsigned)CHBYTES), "r"(mb) : "memory");
}
// one h value (duplicated k-pair for one row) times 8 outputs
__device__ __forceinline__ void row8(ull* a, ull h,
                                     const ulonglong2 &w0, const ulonglong2 &w1,
                                     const ulonglong2 &w2, const ulonglong2 &w3) {
    ffma2(a[0], h, w0.x); ffma2(a[1], h, w0.y);
    ffma2(a[2], h, w1.x); ffma2(a[3], h, w1.y);
    ffma2(a[4], h, w2.x); ffma2(a[5], h, w2.y);
    ffma2(a[6], h, w3.x); ffma2(a[7], h, w3.y);
}

// ---------------- prep: paired fused weight image ----------------
__global__ void prep_kernel(const float* __restrict__ eWh, const float* __restrict__ eWx,
                            const float* __restrict__ dWh, const float* __restrict__ dWx)
{
    int p  = blockIdx.x / KPAD;
    int kp = blockIdx.x % KPAD;
    int d  = threadIdx.x;
    const float* Wh = p ? dWh : eWh;
    const float* Wx = p ? dWx : eWx;
    int k0 = 2 * kp, k1 = 2 * kp + 1;
    float v0 = (k0 < D_) ? Wh[d * D_ + k0] : ((k0 < D_ + C_) ? Wx[d * C_ + (k0 - D_)] : 0.f);
    float v1 = (k1 < D_) ? Wh[d * D_ + k1] : ((k1 < D_ + C_) ? Wx[d * C_ + (k1 - D_)] : 0.f);
    g_Wp[p][kp][d] = make_float2(v0, v1);
}

// ---------------- main persistent kernel ----------------
extern "C" __global__ void __launch_bounds__(NTHR, 1)
seq2seq_kernel(const float* __restrict__ x,
               const float* __restrict__ ebx, const float* __restrict__ dbx,
               const float* __restrict__ dWy, const float* __restrict__ dby,
               float* __restrict__ out)
{
    extern __shared__ ull smu[];
    ull*   smW = smu + U_W;
    ull*   sh  = smu + U_SH;
    ull*   sWy = smu + U_WY;
    ull*   sbe = smu + U_BE;
    ull*   sbd = smu + U_BD;
    float* yt  = (float*)(smu + U_YT);
    float* sby = (float*)(smu + U_BY);

    const int tid  = threadIdx.x;
    const int lane = tid & 31;
    const int warp = tid >> 5;
    const int g8   = lane >> 3;           // output group 0..3
    const int s    = lane & 7;            // row group 0..7
    const int rowbase = blockIdx.x * RB;

    // lane->work map (wavefront-optimal, from R16):
    //   outputs: slots wOff + {0,1, 8,9, 16,17, 24,25}  (wOff = warp*32 + 2*g8)
    //   rows:    {2s, 2s+1, 16+2s, 17+2s}
    const int wOff = warp * 32 + 2 * g8;
    const int hOffA = 2 * s;
    const int hOffB = 16 + 2 * s;

    const unsigned sW_u32 = smem_u32(smu) + U_W * 8;
    const unsigned mb_u32 = smem_u32(smu) + U_MB * 8;   // data[0],data[1],cons[0],cons[1]

    const int c1 = tid >> 5;              // aug staging (tid<192): pair-col, row
    const int r1 = tid & 31;

    // ---- init ----
    for (int i = tid; i < KPAD * RB; i += NTHR) sh[i] = 0ull;
    for (int i = tid; i < 12 * 128; i += NTHR)  sWy[i] = ((const ull*)dWy)[i];
    for (int i = tid; i < D_; i += NTHR) {
        sbe[i] = pk(ebx[i], 0.f);
        sbd[i] = pk(dbx[i], 0.f);
    }
    if (tid < K_) sby[tid] = dby[tid];
    if (tid == 0) {
        mbar_init(mb_u32,      1);   // data0
        mbar_init(mb_u32 + 8,  1);   // data1
        mbar_init(mb_u32 + 16, 8);   // consume0 (8 warps)
        mbar_init(mb_u32 + 24, 8);   // consume1
    }
    __syncthreads();

    // stage x_0 into aug rows (192 slots)
    if (tid < 192) {
        const float2 a = *(const float2*)(x + ((size_t)rowbase + r1) * C_ + 2 * c1);
        sh[(128 + c1) * RB + r1] = pk(a.x, a.y);
    }
    if (tid == 0) {   // prime chunks g=0 (buf0), g=1 (buf1), phase 0
        tma_issue(mb_u32,     sW_u32,           (const char*)g_Wp);
        tma_issue(mb_u32 + 8, sW_u32 + CHBYTES, (const char*)g_Wp + (size_t)CH * D_ * 8);
    }
    __syncthreads();

    ull acc[32];

    for (int t = 0; t < 2 * T_; ++t) {
        const bool dec = (t >= T_);

        // prefetch next x slice into regs (encoder)
        ull xv = 0ull;
        if (!dec && (t + 1) < T_ && tid < 192) {
            const float2 a = *(const float2*)(x + ((size_t)(t + 1) * N_ + rowbase + r1) * C_ + 2 * c1);
            xv = pk(a.x, a.y);
        }

        // acc init = {bias, 0} ; bias slots follow the W slot map
        {
            const ull* bp = (dec ? sbd : sbe) + wOff;
            ulonglong2 b01 = *(const ulonglong2*)(bp);
            ulonglong2 b23 = *(const ulonglong2*)(bp + 8);
            ulonglong2 b45 = *(const ulonglong2*)(bp + 16);
            ulonglong2 b67 = *(const ulonglong2*)(bp + 24);
            ull bj[8] = {b01.x, b01.y, b23.x, b23.y, b45.x, b45.y, b67.x, b67.y};
            #pragma unroll
            for (int i = 0; i < 4; ++i)
                #pragma unroll
                for (int j = 0; j < 8; ++j) acc[i * 8 + j] = bj[j];
        }

        // ---- GEMM: 4 chunks of 34 kp; depth-1 register pipeline;
        //      interior sync via non-blocking consume mbarriers ----
        #pragma unroll 1
        for (int c = 0; c < NCHK; ++c) {
            const int g = t * NCHK + c;
            const int b = g & 1;
            const unsigned par = (unsigned)((g >> 1) & 1);
            mbar_wait(mb_u32 + b * 8, par);   // data arrived

            const ull* wb = smW + (size_t)b * CHW + wOff;
            const ull* hb = sh + (size_t)(c * CH) * RB;

            // prime kp0 into A
            ulonglong2 wA0 = *(const ulonglong2*)(wb);
            ulonglong2 wA1 = *(const ulonglong2*)(wb + 8);
            ulonglong2 wA2 = *(const ulonglong2*)(wb + 16);
            ulonglong2 wA3 = *(const ulonglong2*)(wb + 24);
            ulonglong2 hA0 = *(const ulonglong2*)(hb + hOffA);
            ulonglong2 hA1 = *(const ulonglong2*)(hb + hOffB);

            #pragma unroll 2
            for (int kk = 0; kk < CH - 2; kk += 2) {
                // load kp kk+1 into B
                const ull* wqB = wb + (size_t)(kk + 1) * D_;
                const ull* hqB = hb + (size_t)(kk + 1) * RB;
                ulonglong2 wB0 = *(const ulonglong2*)(wqB);
                ulonglong2 wB1 = *(const ulonglong2*)(wqB + 8);
                ulonglong2 wB2 = *(const ulonglong2*)(wqB + 16);
                ulonglong2 wB3 = *(const ulonglong2*)(wqB + 24);
                ulonglong2 hB0 = *(const ulonglong2*)(hqB + hOffA);
                ulonglong2 hB1 = *(const ulonglong2*)(hqB + hOffB);

                // compute kp kk (A)
                row8(acc + 0,  hA0.x, wA0, wA1, wA2, wA3);
                row8(acc + 8,  hA0.y, wA0, wA1, wA2, wA3);
                row8(acc + 16, hA1.x, wA0, wA1, wA2, wA3);
                row8(acc + 24, hA1.y, wA0, wA1, wA2, wA3);

                // load kp kk+2 into A (kk max = 30 -> kp32, in-bounds)
                const ull* wqA = wb + (size_t)(kk + 2) * D_;
                const ull* hqA = hb + (size_t)(kk + 2) * RB;
                wA0 = *(const ulonglong2*)(wqA);
                wA1 = *(const ulonglong2*)(wqA + 8);
                wA2 = *(const ulonglong2*)(wqA + 16);
                wA3 = *(const ulonglong2*)(wqA + 24);
                hA0 = *(const ulonglong2*)(hqA + hOffA);
                hA1 = *(const ulonglong2*)(hqA + hOffB);

                // compute kp kk+1 (B)
                row8(acc + 0,  hB0.x, wB0, wB1, wB2, wB3);
                row8(acc + 8,  hB0.y, wB0, wB1, wB2, wB3);
                row8(acc + 16, hB1.x, wB0, wB1, wB2, wB3);
                row8(acc + 24, hB1.y, wB0, wB1, wB2, wB3);
            }
            // tail: kp CH-2 (in A regs) and kp CH-1
            {
                const ull* wqB = wb + (size_t)(CH - 1) * D_;
                const ull* hqB = hb + (size_t)(CH - 1) * RB;
                ulonglong2 wB0 = *(const ulonglong2*)(wqB);
                ulonglong2 wB1 = *(const ulonglong2*)(wqB + 8);
                ulonglong2 wB2 = *(const ulonglong2*)(wqB + 16);
                ulonglong2 wB3 = *(const ulonglong2*)(wqB + 24);
                ulonglong2 hB0 = *(const ulonglong2*)(hqB + hOffA);
                ulonglong2 hB1 = *(const ulonglong2*)(hqB + hOffB);

                row8(acc + 0,  hA0.x, wA0, wA1, wA2, wA3);
                row8(acc + 8,  hA0.y, wA0, wA1, wA2, wA3);
                row8(acc + 16, hA1.x, wA0, wA1, wA2, wA3);
                row8(acc + 24, hA1.y, wA0, wA1, wA2, wA3);

                row8(acc + 0,  hB0.x, wB0, wB1, wB2, wB3);
                row8(acc + 8,  hB0.y, wB0, wB1, wB2, wB3);
                row8(acc + 16, hB1.x, wB0, wB1, wB2, wB3);
                row8(acc + 24, hB1.y, wB0, wB1, wB2, wB3);
            }

            // non-blocking consume signal: one arrive per warp
            __syncwarp();
            if (lane == 0) mbar_arrive(mb_u32 + 16 + b * 8);

            // tid0 only: wait full consumption of buffer b, then refill chunk g+2
            if (tid == 0 && (g + 2) < GTOT) {
                mbar_wait(mb_u32 + 16 + b * 8, par);   // consume parity == data parity
                const int g2 = g + 2;
                const int t2 = g2 >> 2, c2 = g2 & 3;
                const int ph = (t2 >= T_) ? 1 : 0;
                tma_issue(mb_u32 + b * 8, sW_u32 + b * CHBYTES,
                          (const char*)g_Wp + ((size_t)ph * KPAD + c2 * CH) * D_ * 8);
            }
        }

        __syncthreads();   // S1: all GEMM reads of h/aug done

        // ---- epilogue: h = relu(lo+hi), store paired h ----
        #pragma unroll
        for (int j2 = 0; j2 < 4; ++j2) {
            const int m = 16 * warp + 4 * j2 + g8;
            float a0, b0, a1, b1, a2, b2, a3, b3;
            unpack2(acc[0 * 8 + 2 * j2],     a0, b0);
            unpack2(acc[0 * 8 + 2 * j2 + 1], a1, b1);
            unpack2(acc[1 * 8 + 2 * j2],     a2, b2);
            unpack2(acc[1 * 8 + 2 * j2 + 1], a3, b3);
            *(float4*)(sh + (size_t)m * RB + hOffA) =
                make_float4(fmaxf(a0 + b0, 0.f), fmaxf(a1 + b1, 0.f),
                            fmaxf(a2 + b2, 0.f), fmaxf(a3 + b3, 0.f));
            unpack2(acc[2 * 8 + 2 * j2],     a0, b0);
            unpack2(acc[2 * 8 + 2 * j2 + 1], a1, b1);
            unpack2(acc[3 * 8 + 2 * j2],     a2, b2);
            unpack2(acc[3 * 8 + 2 * j2 + 1], a3, b3);
            *(float4*)(sh + (size_t)m * RB + hOffB) =
                make_float4(fmaxf(a0 + b0, 0.f), fmaxf(a1 + b1, 0.f),
                            fmaxf(a2 + b2, 0.f), fmaxf(a3 + b3, 0.f));
        }
        if (tid < 192) {
            if (!dec) {   // stage x_{t+1} or SOS (col 10 -> pair 5 = {1,0})
                sh[(128 + c1) * RB + r1] =
                    (t + 1 < T_) ? xv : ((c1 == 5) ? pk(1.f, 0.f) : 0ull);
            } else {      // clear previous one-hot
                sh[(128 + c1) * RB + r1] = 0ull;
            }
        }
        __syncthreads();   // S2: new h (+aug/zero) visible

        // ---- decoder: tiled y = h @ Wy^T + by, argmax, one-hot feedback ----
        if (dec) {
            const int kg = lane & 3;          // k in {kg, kg+4, kg+8}
            const int mg = lane >> 2;         // m-chunk [16*mg, 16*mg+16)
            const ull* hb = sh + 4 * warp;    // rows 4*warp..+3 of NEW h
            const ull* w0 = sWy + kg * 128;
            const ull* w1 = sWy + (kg + 4) * 128;
            const ull* w2 = sWy + (kg + 8) * 128;
            ull a[12];
            #pragma unroll
            for (int q = 0; q < 12; ++q) a[q] = 0ull;
            const int mbase = mg * 16;
            #pragma unroll 4
            for (int mm = 0; mm < 16; ++mm) {
                const int m = mbase + mm;
                const ulonglong2* hp = (const ulonglong2*)(hb + (size_t)m * RB);
                ulonglong2 hA = hp[0], hB = hp[1];
                ull hr[4] = {hA.x, hA.y, hB.x, hB.y};
                ull wv0 = w0[m], wv1 = w1[m], wv2 = w2[m];
                #pragma unroll
                for (int i = 0; i < 4; ++i) {
                    ffma2(a[i * 3 + 0], hr[i], wv0);
                    ffma2(a[i * 3 + 1], hr[i], wv1);
                    ffma2(a[i * 3 + 2], hr[i], wv2);
                }
            }
            float v[12];
            #pragma unroll
            for (int q = 0; q < 12; ++q) {
                float lo, hi; unpack2(a[q], lo, hi);
                v[q] = lo + hi;
            }
            #pragma unroll
            for (int q = 0; q < 12; ++q) {
                v[q] += shflx(v[q], 4);
                v[q] += shflx(v[q], 8);
                v[q] += shflx(v[q], 16);
            }
            if (mg == 0) {
                #pragma unroll
                for (int i = 0; i < 4; ++i) {
                    yt[(4 * warp + i) * 12 + kg]     = v[i * 3 + 0] + sby[kg];
                    yt[(4 * warp + i) * 12 + kg + 4] = v[i * 3 + 1] + sby[kg + 4];
                    yt[(4 * warp + i) * 12 + kg + 8] = v[i * 3 + 2] + sby[kg + 8];
                }
            }
            __syncthreads();   // yt complete
            if (tid < 32) {
                const float* yr = yt + tid * 12;
                float vv[12];
                #pragma unroll
                for (int q = 0; q < 3; ++q) {
                    float4 fv = *(const float4*)(yr + 4 * q);
                    vv[4 * q] = fv.x; vv[4 * q + 1] = fv.y;
                    vv[4 * q + 2] = fv.z; vv[4 * q + 3] = fv.w;
                }
                float best = vv[0]; int sel = 0;
                #pragma unroll
                for (int q = 1; q < 12; ++q)
                    if (vv[q] > best) { best = vv[q]; sel = q; }   // first-max wins
                float* og = out + ((size_t)(t - T_) * N_ + rowbase + tid) * K_;
                *(float4*)(og)     = make_float4(vv[0], vv[1], vv[2],  vv[3]);
                *(float4*)(og + 4) = make_float4(vv[4], vv[5], vv[6],  vv[7]);
                *(float4*)(og + 8) = make_float4(vv[8], vv[9], vv[10], vv[11]);
                sh[(128 + (sel >> 1)) * RB + tid] = (sel & 1) ? pk(0.f, 1.f) : pk(1.f, 0.f);
            }
            __syncthreads();   // one-hot visible before next step's aug reads
        }
    }
}

extern "C" void kernel_launch(void* const* d_in, const int* in_sizes, int n_in,
                              void* d_out, int out_size) {
    const float* x   = (const float*)d_in[0];
    const float* eWx = (const float*)d_in[1];
    const float* ebx = (const float*)d_in[2];
    const float* eWh = (const float*)d_in[3];
    const float* dWx = (const float*)d_in[6];
    const float* dbx = (const float*)d_in[7];
    const float* dWh = (const float*)d_in[8];
    const float* dWy = (const float*)d_in[9];
    const float* dby = (const float*)d_in[10];

    prep_kernel<<<2 * KPAD, D_>>>(eWh, eWx, dWh, dWx);

    cudaFuncSetAttribute(seq2seq_kernel,
                         cudaFuncAttributeMaxDynamicSharedMemorySize, SMEM_BYTES);
    seq2seq_kernel<<<NBLK, NTHR, SMEM_BYTES>>>(
        x, ebx, dbx, dWy, dby, (float*)d_out);
}